// round 16
// baseline (speedup 1.0000x reference)
#include <cuda_runtime.h>
#include <cuda_fp16.h>
#include <cstdint>

// ---------------------------------------------------------------------------
// B=32, CIN=256, COUT=256, 64x64 -> 32x32, 3x3 stride2 pad1 conv. Crop mask
// all-True => plain conv. Single-pass fp16 m16n8k16 implicit GEMM.
// Round 16: ONE persistent kernel (296 CTAs = 2/SM):
//   phase 1: transform (weights fp16 + x transpose/convert) via CTA loops
//   grid barrier (epoch-monotonic, replay-safe)
//   phase 2: R13 conv pipeline (KC=96, 2-stage, paired iters), static tiles.
// ---------------------------------------------------------------------------

#define B_    32
#define CIN_  256
#define COUT_ 256
#define H_    64
#define W_    64
#define HW_   4096
#define NPIX_ 1024
#define KTOT  2304

#define BM 128
#define BN 128
#define KC 96
#define NIT 24                 // 2304 / 96
#define NCTA 296
#define NTILES 512
#define NTRF (2304 + 32768)    // transform work items

#define ROW_B    208           // 192B payload + 16B pad
#define A_OFF    0
#define B_OFF2   (128 * ROW_B)             // 26624
#define STAGE_B  (B_OFF2 + 128 * ROW_B)    // 53248
#define TILES_OFF 1024
#define NSTAGE   2
#define SMEM_TOTAL (TILES_OFF + NSTAGE * STAGE_B)   // 107520 (x2 CTAs = 215040)

__device__ __align__(128) __half g_A[COUT_ * KTOT];             // [cout][p*256+cin]
__device__ __align__(128) __half g_X[(size_t)B_ * HW_ * CIN_];  // [b][s][cin]
__device__ unsigned int g_bar;   // monotonic grid barrier (never reset)

// ---------------------------------------------------------------------------
__device__ __forceinline__ uint32_t smem_u32(const void* p) {
    uint32_t a;
    asm("{ .reg .u64 t; cvta.to.shared.u64 t, %1; cvt.u32.u64 %0, t; }" : "=r"(a) : "l"(p));
    return a;
}
__device__ __forceinline__ void bulk_g2s(uint32_t dst, const void* src, uint32_t bytes,
                                         uint32_t mbar) {
    asm volatile(
        "cp.async.bulk.shared::cluster.global.mbarrier::complete_tx::bytes "
        "[%0], [%1], %2, [%3];"
        :: "r"(dst), "l"(src), "r"(bytes), "r"(mbar) : "memory");
}
__device__ __forceinline__ void mbar_init(uint32_t a, uint32_t cnt) {
    asm volatile("mbarrier.init.shared.b64 [%0], %1;" :: "r"(a), "r"(cnt) : "memory");
}
__device__ __forceinline__ void mbar_expect_tx(uint32_t a, uint32_t tx) {
    asm volatile("mbarrier.arrive.expect_tx.shared.b64 _, [%0], %1;"
                 :: "r"(a), "r"(tx) : "memory");
}
__device__ __forceinline__ void mbar_wait(uint32_t a, uint32_t parity) {
    asm volatile(
        "{\n\t.reg .pred P1;\n\t"
        "W_%=:\n\t"
        "mbarrier.try_wait.parity.acquire.cta.shared::cta.b64 P1, [%0], %1, 0x989680;\n\t"
        "@!P1 bra W_%=;\n\t}"
        :: "r"(a), "r"(parity) : "memory");
}
__device__ __forceinline__ void mma_fp16(float* d, const uint32_t* a, uint32_t b0, uint32_t b1) {
    asm volatile(
        "mma.sync.aligned.m16n8k16.row.col.f32.f16.f16.f32 "
        "{%0,%1,%2,%3}, {%4,%5,%6,%7}, {%8,%9}, {%0,%1,%2,%3};"
        : "+f"(d[0]), "+f"(d[1]), "+f"(d[2]), "+f"(d[3])
        : "r"(a[0]), "r"(a[1]), "r"(a[2]), "r"(a[3]), "r"(b0), "r"(b1));
}
__device__ __forceinline__ void ldm4(uint32_t* r, uint32_t addr) {
    asm volatile("ldmatrix.sync.aligned.m8n8.x4.shared.b16 {%0,%1,%2,%3}, [%4];"
                 : "=r"(r[0]), "=r"(r[1]), "=r"(r[2]), "=r"(r[3]) : "r"(addr));
}

// ---------------------------------------------------------------------------
// One persistent kernel: transform -> grid barrier -> conv
// ---------------------------------------------------------------------------
__global__ void __launch_bounds__(256, 2) fused_kernel(const float* __restrict__ x,
                                                       const float* __restrict__ w,
                                                       float* __restrict__ out) {
    extern __shared__ char smem[];
    const uint32_t sb = smem_u32(smem);
    const int tid = threadIdx.x;
    const int lane = tid & 31, warp = tid >> 5;

    if (tid < NSTAGE) mbar_init(sb + tid * 16, 1);

    // ======================= phase 1: transform =======================
    {
        float* tile = (float*)(smem + TILES_OFF);   // [32][33] floats
#pragma unroll 1
        for (int t = blockIdx.x; t < NTRF; t += NCTA) {
            if (t < 2304) {
                int idx = t * 256 + tid;            // linear over [cout][p][cin]
                int cin = idx & 255;
                int p = (idx >> 8) % 9;
                int cout = idx / KTOT;
                g_A[idx] = __float2half_rn(w[cout * KTOT + cin * 9 + p]);
            } else {
                const int tt = t - 2304;
                const int s0 = (tt & 127) * 32;
                const int c0 = ((tt >> 7) & 7) * 32;
                const int b = tt >> 10;
                const int tx = tid & 31, ty = tid >> 5;   // 32 x 8
                const float* xb = x + ((size_t)b * CIN_ + c0) * HW_ + s0;
#pragma unroll
                for (int k = 0; k < 4; ++k)
                    tile[(ty + 8 * k) * 33 + tx] = xb[(size_t)(ty + 8 * k) * HW_ + tx];
                __syncthreads();
                if (tid < 128) {
                    const int s = tid >> 2;
                    const int c = (tid & 3) * 8;
                    __half2 h0 = __floats2half2_rn(tile[(c + 0) * 33 + s], tile[(c + 1) * 33 + s]);
                    __half2 h1 = __floats2half2_rn(tile[(c + 2) * 33 + s], tile[(c + 3) * 33 + s]);
                    __half2 h2 = __floats2half2_rn(tile[(c + 4) * 33 + s], tile[(c + 5) * 33 + s]);
                    __half2 h3 = __floats2half2_rn(tile[(c + 6) * 33 + s], tile[(c + 7) * 33 + s]);
                    uint4 v;
                    v.x = *(uint32_t*)&h0; v.y = *(uint32_t*)&h1;
                    v.z = *(uint32_t*)&h2; v.w = *(uint32_t*)&h3;
                    size_t o = ((size_t)b * HW_ + s0 + s) * CIN_ + c0 + c;
                    *(uint4*)(g_X + o) = v;
                }
                __syncthreads();
            }
        }
    }

    // ======================= grid barrier (epoch-monotonic) =======================
    __syncthreads();
    {
        __shared__ unsigned int s_target;
        if (tid == 0) {
            __threadfence();
            unsigned int old = atomicAdd(&g_bar, 1u);
            s_target = old - (old % NCTA) + NCTA;
        }
        __syncthreads();
        if (tid == 0) {
            while (atomicAdd(&g_bar, 0u) < s_target) __nanosleep(128);
        }
        __syncthreads();
        __threadfence();
    }
    asm volatile("fence.proxy.async.shared::cta;" ::: "memory");

    // ======================= phase 2: conv =======================
    const int mw = (warp >> 1) * 32;      // 0,32,64,96
    const int nw = (warp & 1) * 64;       // 0,64
    uint32_t aOff[2], bOff[4];
#pragma unroll
    for (int mi = 0; mi < 2; ++mi)
        aOff[mi] = (uint32_t)(A_OFF + (mw + mi * 16 + (lane & 15)) * ROW_B
                   + (lane >> 4) * 16);
#pragma unroll
    for (int nj = 0; nj < 4; ++nj)
        bOff[nj] = (uint32_t)(B_OFF2
                 + (nw + nj * 16 + (lane & 7) + (lane >> 4) * 8) * ROW_B
                 + ((lane >> 3) & 1) * 16);
    const int lg = lane >> 2;
    const int lc = lane & 3;

    int ph = 0;    // persistent across tiles (12 flips per stage per tile: even)

#pragma unroll 1
    for (int tile_id = blockIdx.x; tile_id < NTILES; tile_id += NCTA) {
        const int m0 = (tile_id & 1) * BM;
        const int nt = tile_id >> 1;
        const int b = nt >> 3;
        const int pix0 = (nt & 7) * BN;

        const int pixL = pix0 + (tid & 127);
        const int ohL = pixL >> 5, owL = pixL & 31;
        const __half* gX0 = g_X + (size_t)b * HW_ * CIN_;

        auto inv_rows = [&](int p) -> int {
            const int kh = p / 3, kw = p - (p / 3) * 3;
            int inv = (kw == 0 ? 4 : 0) + ((kh == 0 && pix0 == 0) ? 32 : 0);
            if (kw == 0 && kh == 0 && pix0 == 0) inv -= 1;
            return inv;
        };

        auto load_stage = [&](int buf, int it) {
            const int k0 = it * KC;
            const int p1 = k0 >> 8;
            const int o1 = k0 & 255;
            const int len1 = (256 - o1 < KC) ? (256 - o1) : KC;
            const int len2 = KC - len1;
            const uint32_t st = sb + TILES_OFF + buf * STAGE_B;
            const uint32_t mb = sb + buf * 16;
            if (tid == 0) {
                uint32_t txB = 2u * (uint32_t)len1 * (uint32_t)(128 - inv_rows(p1));
                if (len2) txB += 2u * (uint32_t)len2 * (uint32_t)(128 - inv_rows(p1 + 1));
                mbar_expect_tx(mb, 128u * 192u + txB);
            }
            const int r = tid & 127;
            if (tid < 128) {
                bulk_g2s(st + A_OFF + r * ROW_B,
                         g_A + (size_t)(m0 + r) * KTOT + k0, KC * 2, mb);
            } else {
                const uint32_t dst = st + B_OFF2 + r * ROW_B;
                {
                    const int kh = p1 / 3, kw = p1 - (p1 / 3) * 3;
                    const int ih = ohL * 2 - 1 + kh;
                    const int iw = owL * 2 - 1 + kw;
                    if (((unsigned)ih < (unsigned)H_) && ((unsigned)iw < (unsigned)W_)) {
                        bulk_g2s(dst, gX0 + (size_t)(ih * W_ + iw) * CIN_ + o1, len1 * 2, mb);
                    } else {
                        for (int j = 0; j < len1 * 2; j += 16)
                            asm volatile("st.shared.v4.b32 [%0], {%1, %1, %1, %1};"
                                         :: "r"(dst + j), "r"(0u) : "memory");
                    }
                }
                if (len2) {
                    const int p2 = p1 + 1;
                    const int kh = p2 / 3, kw = p2 - (p2 / 3) * 3;
                    const int ih = ohL * 2 - 1 + kh;
                    const int iw = owL * 2 - 1 + kw;
                    const uint32_t d2 = dst + len1 * 2;
                    if (((unsigned)ih < (unsigned)H_) && ((unsigned)iw < (unsigned)W_)) {
                        bulk_g2s(d2, gX0 + (size_t)(ih * W_ + iw) * CIN_, len2 * 2, mb);
                    } else {
                        for (int j = 0; j < len2 * 2; j += 16)
                            asm volatile("st.shared.v4.b32 [%0], {%1, %1, %1, %1};"
                                         :: "r"(d2 + j), "r"(0u) : "memory");
                    }
                }
            }
        };

        float acc[2][8][4];
#pragma unroll
        for (int mi = 0; mi < 2; ++mi)
#pragma unroll
            for (int ni = 0; ni < 8; ++ni)
#pragma unroll
                for (int j = 0; j < 4; ++j) acc[mi][ni][j] = 0.0f;

        load_stage(0, 0);
        load_stage(1, 1);
        __syncthreads();   // zero-STS of initial stages visible

        auto compute_stage = [&](int buf) {
            const uint32_t st = sb + TILES_OFF + buf * STAGE_B;
#pragma unroll
            for (int ks = 0; ks < 6; ++ks) {
                const uint32_t kb = (uint32_t)(ks * 32);
                uint32_t a[2][4], bf[4][4];
#pragma unroll
                for (int mi = 0; mi < 2; ++mi)
                    ldm4(a[mi], st + aOff[mi] + kb);
#pragma unroll
                for (int nj = 0; nj < 4; ++nj)
                    ldm4(bf[nj], st + bOff[nj] + kb);
#pragma unroll
                for (int nj = 0; nj < 4; ++nj)
#pragma unroll
                    for (int s2 = 0; s2 < 2; ++s2) {
                        const int ni = nj * 2 + s2;
                        const uint32_t b0 = bf[nj][s2 * 2];
                        const uint32_t b1 = bf[nj][s2 * 2 + 1];
#pragma unroll
                        for (int mi = 0; mi < 2; ++mi)
                            mma_fp16(acc[mi][ni], a[mi], b0, b1);
                    }
            }
        };

#pragma unroll 1
        for (int jp = 0; jp < NIT / 2; ++jp) {
            mbar_wait(sb + 0 * 16, ph);
            compute_stage(0);
            mbar_wait(sb + 1 * 16, ph);
            compute_stage(1);
            ph ^= 1;
            __syncthreads();                      // both stages drained
            if (2 * jp + 2 < NIT) {
                load_stage(0, 2 * jp + 2);
                load_stage(1, 2 * jp + 3);
            }
        }

        // ---- epilogue for this tile ----
        float* ob = out + (size_t)b * COUT_ * NPIX_;
#pragma unroll
        for (int mi = 0; mi < 2; ++mi) {
            const int cout0 = m0 + mw + mi * 16 + lg;
#pragma unroll
            for (int ni = 0; ni < 8; ++ni) {
                const int nc = pix0 + nw + ni * 8 + lc * 2;
                float2* p0 = (float2*)(ob + (size_t)cout0 * NPIX_ + nc);
                float2* p1 = (float2*)(ob + (size_t)(cout0 + 8) * NPIX_ + nc);
                *p0 = make_float2(acc[mi][ni][0], acc[mi][ni][1]);
                *p1 = make_float2(acc[mi][ni][2], acc[mi][ni][3]);
            }
        }
        __syncthreads();    // tiles reuse smem stages; keep CTA converged
    }
}

// ---------------------------------------------------------------------------
extern "C" void kernel_launch(void* const* d_in, const int* in_sizes, int n_in,
                              void* d_out, int out_size) {
    const float* x = (const float*)d_in[0];   // [32,256,64,64]
    const float* w = (const float*)d_in[1];   // [256,256,3,3]
    float* out = (float*)d_out;               // [32,256,32,32]

    cudaFuncSetAttribute(fused_kernel,
                         cudaFuncAttributeMaxDynamicSharedMemorySize, SMEM_TOTAL);
    fused_kernel<<<NCTA, 256, SMEM_TOTAL>>>(x, w, out);
}